// round 6
// baseline (speedup 1.0000x reference)
#include <cuda_runtime.h>
#include <cuda_bf16.h>
#include <math.h>

// Problem dims (fixed by the dataset)
#define NB 4
#define CH 3
#define HH 1080
#define WW 1920
#define HW (HH * WW)
#define NHW (NB * HW)

#define SZ_IN     (NB * 3 * HW)   // 24883200
#define SZ_FLOW   (NB * 2 * HW)   // 16588800
#define SZ_METRIC (NB * 1 * HW)   //  8294400

// Accumulator: [N, H, W, 4] interleaved (c0*m*w, c1*m*w, c2*m*w, m*w).
// Starts zeroed (BSS). norm_kernel re-zeroes every cell after reading it, so
// the "all zero at entry" invariant holds for every kernel_launch call /
// graph replay — no separate zero pass needed.
__device__ float g_acc[(size_t)NHW * 4];

__global__ void splat_kernel(const float* __restrict__ in,
                             const float* __restrict__ flow,
                             const float* __restrict__ metric) {
    int t = blockIdx.x * blockDim.x + threadIdx.x;
    if (t >= NHW / 4) return;
    int p0   = t * 4;
    int b    = p0 / HW;
    int rem0 = p0 - b * HW;
    int y    = rem0 / WW;          // W divisible by 4 -> all 4 px same row
    int xb   = rem0 - y * WW;

    const float4 fx4 = *reinterpret_cast<const float4*>(flow + (size_t)(b * 2 + 0) * HW + rem0);
    const float4 fy4 = *reinterpret_cast<const float4*>(flow + (size_t)(b * 2 + 1) * HW + rem0);
    const float4 mm4 = *reinterpret_cast<const float4*>(metric + (size_t)b * HW + rem0);
    const float4 c04 = *reinterpret_cast<const float4*>(in + (size_t)(b * 3 + 0) * HW + rem0);
    const float4 c14 = *reinterpret_cast<const float4*>(in + (size_t)(b * 3 + 1) * HW + rem0);
    const float4 c24 = *reinterpret_cast<const float4*>(in + (size_t)(b * 3 + 2) * HW + rem0);

    const float fxs[4] = {fx4.x, fx4.y, fx4.z, fx4.w};
    const float fys[4] = {fy4.x, fy4.y, fy4.z, fy4.w};
    const float mms[4] = {mm4.x, mm4.y, mm4.z, mm4.w};
    const float c0s[4] = {c04.x, c04.y, c04.z, c04.w};
    const float c1s[4] = {c14.x, c14.y, c14.z, c14.w};
    const float c2s[4] = {c24.x, c24.y, c24.z, c24.w};

    float* base = g_acc + (size_t)b * HW * 4;

#pragma unroll
    for (int j = 0; j < 4; j++) {
        float tx = (float)(xb + j) + fxs[j];
        float ty = (float)y + fys[j];
        if (!isfinite(tx) || !isfinite(ty)) continue;  // ref zeroes these

        float m  = __expf(mms[j]);
        float v0 = c0s[j] * m;
        float v1 = c1s[j] * m;
        float v2 = c2s[j] * m;

        float fxf = floorf(tx);
        float fyf = floorf(ty);
        int x0 = (int)fxf;
        int y0 = (int)fyf;
        float ax = tx - fxf;
        float ay = ty - fyf;

        float wx[2] = {1.f - ax, ax};
        float wy[2] = {1.f - ay, ay};

#pragma unroll
        for (int dy = 0; dy < 2; dy++) {
            int iy = y0 + dy;
            if (iy < 0 || iy >= HH) continue;
#pragma unroll
            for (int dx = 0; dx < 2; dx++) {
                int ix = x0 + dx;
                if (ix < 0 || ix >= WW) continue;
                float w = wx[dx] * wy[dy];
                float* ptr = base + ((size_t)iy * WW + ix) * 4;
                // One 16B vector reduction per corner; 4th lane accumulates
                // m*w (the reference's splatted exp(metric) channel).
                asm volatile(
                    "red.global.add.v4.f32 [%0], {%1, %2, %3, %4};"
                    :: "l"(ptr), "f"(v0 * w), "f"(v1 * w), "f"(v2 * w), "f"(m * w)
                    : "memory");
            }
        }
    }
}

// Reads acc, normalizes into out, and re-zeroes acc for the next call.
__global__ void norm_kernel(float* __restrict__ out) {
    int t = blockIdx.x * blockDim.x + threadIdx.x;
    if (t >= NHW / 4) return;
    int p0   = t * 4;
    int b    = p0 / HW;
    int rem0 = p0 - b * HW;

    float4* acc4 = reinterpret_cast<float4*>(g_acc) + p0;
    float4 o0, o1, o2;
    const float4 z = make_float4(0.f, 0.f, 0.f, 0.f);

    float4 a0 = acc4[0]; acc4[0] = z;
    float4 a1 = acc4[1]; acc4[1] = z;
    float4 a2 = acc4[2]; acc4[2] = z;
    float4 a3 = acc4[3]; acc4[3] = z;

    float i0 = 1.0f / (a0.w + 1e-7f);
    float i1 = 1.0f / (a1.w + 1e-7f);
    float i2 = 1.0f / (a2.w + 1e-7f);
    float i3 = 1.0f / (a3.w + 1e-7f);

    o0 = make_float4(a0.x * i0, a1.x * i1, a2.x * i2, a3.x * i3);
    o1 = make_float4(a0.y * i0, a1.y * i1, a2.y * i2, a3.y * i3);
    o2 = make_float4(a0.z * i0, a1.z * i1, a2.z * i2, a3.z * i3);

    *reinterpret_cast<float4*>(out + (size_t)(b * 3 + 0) * HW + rem0) = o0;
    *reinterpret_cast<float4*>(out + (size_t)(b * 3 + 1) * HW + rem0) = o1;
    *reinterpret_cast<float4*>(out + (size_t)(b * 3 + 2) * HW + rem0) = o2;
}

extern "C" void kernel_launch(void* const* d_in, const int* in_sizes, int n_in,
                              void* d_out, int out_size) {
    // Identify inputs by element count — robust to any metadata ordering.
    const float* tenIn     = nullptr;
    const float* tenFlow   = nullptr;
    const float* tenMetric = nullptr;
    for (int i = 0; i < n_in; i++) {
        if      (in_sizes[i] == SZ_IN)     tenIn     = (const float*)d_in[i];
        else if (in_sizes[i] == SZ_FLOW)   tenFlow   = (const float*)d_in[i];
        else if (in_sizes[i] == SZ_METRIC) tenMetric = (const float*)d_in[i];
    }
    float* out = (float*)d_out;

    const int threads = 256;
    const int blocks  = (NHW / 4 + threads - 1) / threads;  // 8100

    splat_kernel<<<blocks, threads>>>(tenIn, tenFlow, tenMetric);
    norm_kernel <<<blocks, threads>>>(out);
}

// round 7
// speedup vs baseline: 1.4281x; 1.4281x over previous
#include <cuda_runtime.h>
#include <cuda_bf16.h>
#include <math.h>

// Problem dims (fixed by the dataset)
#define NB 4
#define CH 3
#define HH 1080
#define WW 1920
#define HW (HH * WW)
#define NHW (NB * HW)

#define SZ_IN     (NB * 3 * HW)   // 24883200
#define SZ_FLOW   (NB * 2 * HW)   // 16588800
#define SZ_METRIC (NB * 1 * HW)   //  8294400

// Accumulator: [N, H, W, 4] interleaved (c0*m*w, c1*m*w, c2*m*w, m*w sums).
__device__ float g_acc[(size_t)NHW * 4];

__global__ void zero_kernel(int b) {
    int i = blockIdx.x * blockDim.x + threadIdx.x;
    if (i < HW) {
        float4 z = make_float4(0.f, 0.f, 0.f, 0.f);
        reinterpret_cast<float4*>(g_acc)[(size_t)b * HW + i] = z;
    }
}

__global__ void splat_kernel(const float* __restrict__ in,
                             const float* __restrict__ flow,
                             const float* __restrict__ metric,
                             int b) {
    int rem = blockIdx.x * blockDim.x + threadIdx.x;
    if (rem >= HW) return;
    int y = rem / WW;
    int x = rem - y * WW;

    float fx = flow[(size_t)(b * 2 + 0) * HW + rem];
    float fy = flow[(size_t)(b * 2 + 1) * HW + rem];
    float tx = (float)x + fx;
    float ty = (float)y + fy;
    if (!isfinite(tx) || !isfinite(ty)) return;  // ref zeroes these contributions

    float m  = __expf(metric[(size_t)b * HW + rem]);
    float v0 = in[(size_t)(b * 3 + 0) * HW + rem] * m;
    float v1 = in[(size_t)(b * 3 + 1) * HW + rem] * m;
    float v2 = in[(size_t)(b * 3 + 2) * HW + rem] * m;

    float fxf = floorf(tx);
    float fyf = floorf(ty);
    int x0 = (int)fxf;
    int y0 = (int)fyf;
    float ax = tx - fxf;
    float ay = ty - fyf;

    float wx[2] = {1.f - ax, ax};
    float wy[2] = {1.f - ay, ay};

    float* base = g_acc + (size_t)b * HW * 4;

#pragma unroll
    for (int dy = 0; dy < 2; dy++) {
        int iy = y0 + dy;
        if (iy < 0 || iy >= HH) continue;
#pragma unroll
        for (int dx = 0; dx < 2; dx++) {
            int ix = x0 + dx;
            if (ix < 0 || ix >= WW) continue;
            float w = wx[dx] * wy[dy];
            float* ptr = base + ((size_t)iy * WW + ix) * 4;
            // One 16B vector reduction per corner; 4th lane accumulates m*w
            // (the reference's splatted exp(metric) channel).
            asm volatile(
                "red.global.add.v4.f32 [%0], {%1, %2, %3, %4};"
                :: "l"(ptr), "f"(v0 * w), "f"(v1 * w), "f"(v2 * w), "f"(m * w)
                : "memory");
        }
    }
}

__global__ void norm_kernel(float* __restrict__ out, int b) {
    int rem = blockIdx.x * blockDim.x + threadIdx.x;
    if (rem >= HW) return;
    float4 a = reinterpret_cast<const float4*>(g_acc)[(size_t)b * HW + rem];
    float inv = 1.0f / (a.w + 1e-7f);
    out[(size_t)(b * 3 + 0) * HW + rem] = a.x * inv;
    out[(size_t)(b * 3 + 1) * HW + rem] = a.y * inv;
    out[(size_t)(b * 3 + 2) * HW + rem] = a.z * inv;
}

extern "C" void kernel_launch(void* const* d_in, const int* in_sizes, int n_in,
                              void* d_out, int out_size) {
    // Identify inputs by element count — robust to any metadata ordering.
    const float* tenIn     = nullptr;
    const float* tenFlow   = nullptr;
    const float* tenMetric = nullptr;
    for (int i = 0; i < n_in; i++) {
        if      (in_sizes[i] == SZ_IN)     tenIn     = (const float*)d_in[i];
        else if (in_sizes[i] == SZ_FLOW)   tenFlow   = (const float*)d_in[i];
        else if (in_sizes[i] == SZ_METRIC) tenMetric = (const float*)d_in[i];
    }
    float* out = (float*)d_out;

    // One-time resource init (streams/events only; no device memory).
    // Every call performs identical GPU work.
    static cudaStream_t s2 = nullptr;
    static cudaEvent_t ev_root, ev_z[NB], ev_s[NB], ev_join;
    if (s2 == nullptr) {
        cudaStreamCreateWithFlags(&s2, cudaStreamNonBlocking);
        cudaEventCreateWithFlags(&ev_root, cudaEventDisableTiming);
        cudaEventCreateWithFlags(&ev_join, cudaEventDisableTiming);
        for (int b = 0; b < NB; b++) {
            cudaEventCreateWithFlags(&ev_z[b], cudaEventDisableTiming);
            cudaEventCreateWithFlags(&ev_s[b], cudaEventDisableTiming);
        }
    }

    const int threads = 256;
    const int blocks  = (HW + threads - 1) / threads;  // 8100 per image

    // Fork side stream s2 off the (capture) default stream.
    cudaEventRecord(ev_root, 0);
    cudaStreamWaitEvent(s2, ev_root, 0);

    // s2: pre-zero batches 1..3 concurrently with batch-0 work on stream 0.
    for (int b = 1; b < NB; b++) {
        zero_kernel<<<blocks, threads, 0, s2>>>(b);
        cudaEventRecord(ev_z[b], s2);
    }

    // stream 0: zero(0) then the splat chain (critical path = atomic phase).
    zero_kernel<<<blocks, threads>>>(0);
    for (int b = 0; b < NB; b++) {
        if (b > 0) cudaStreamWaitEvent(0, ev_z[b], 0);
        splat_kernel<<<blocks, threads>>>(tenIn, tenFlow, tenMetric, b);
        cudaEventRecord(ev_s[b], 0);
        // s2: normalize batch b as soon as its splat is done, overlapped
        // with the next batch's splat on stream 0.
        cudaStreamWaitEvent(s2, ev_s[b], 0);
        norm_kernel<<<blocks, threads, 0, s2>>>(out, b);
    }

    // Join s2 back into the capture stream.
    cudaEventRecord(ev_join, s2);
    cudaStreamWaitEvent(0, ev_join, 0);
}